// round 15
// baseline (speedup 1.0000x reference)
#include <cuda_runtime.h>
#include <cuda_bf16.h>
#include <math.h>

#define SEQ   512
#define BATCH 64
#define DIM   512
#define G4    2048
#define NT    8
#define HD    64
#define TL    64
#define MROWS (SEQ*BATCH)

__device__ float g_xg [(size_t)MROWS*G4];    // TRANSPOSED: [s][n=2048][b=64]
__device__ float g_val[(size_t)MROWS*DIM];
__device__ float g_ro [(size_t)MROWS*DIM];
__device__ __nv_bfloat16 g_hhh[(size_t)(SEQ+1)*BATCH*DIM];  // h hi history [s][b][k]
__device__ __nv_bfloat16 g_hhl[(size_t)(SEQ+1)*BATCH*DIM];  // h lo history
__device__ unsigned g_bar;

__device__ __forceinline__ float sigf(float x){ return 1.f/(1.f+__expf(-x)); }

__device__ __forceinline__ void cp16(void* dst_smem, const void* src){
  unsigned d = (unsigned)__cvta_generic_to_shared(dst_smem);
  asm volatile("cp.async.ca.shared.global [%0], [%1], 16;\n" :: "r"(d), "l"(src));
}
#define CP_COMMIT() asm volatile("cp.async.commit_group;\n" ::: "memory")
#define CP_WAIT0()  asm volatile("cp.async.wait_group 0;\n" ::: "memory")

__global__ void init_kernel(){
  unsigned i = blockIdx.x*256u + threadIdx.x;
  if (i==0) g_bar = 0u;
  if (i < DIM*BATCH){
    g_hhh[i] = __float2bfloat16(0.f);
    g_hhl[i] = __float2bfloat16(0.f);
  }
}

// ================= bf16-split tensor GEMM (validated) ========================
#define GSTRIDE 24

__device__ __forceinline__ void cvt_store(__nv_bfloat16* Hp, __nv_bfloat16* Lp, float4 v){
  __nv_bfloat16 h0=__float2bfloat16(v.x), h1=__float2bfloat16(v.y);
  __nv_bfloat16 h2=__float2bfloat16(v.z), h3=__float2bfloat16(v.w);
  __nv_bfloat16 l0=__float2bfloat16(v.x-__bfloat162float(h0));
  __nv_bfloat16 l1=__float2bfloat16(v.y-__bfloat162float(h1));
  __nv_bfloat16 l2=__float2bfloat16(v.z-__bfloat162float(h2));
  __nv_bfloat16 l3=__float2bfloat16(v.w-__bfloat162float(h3));
  ((__nv_bfloat162*)Hp)[0] = __nv_bfloat162(h0,h1);
  ((__nv_bfloat162*)Hp)[1] = __nv_bfloat162(h2,h3);
  ((__nv_bfloat162*)Lp)[0] = __nv_bfloat162(l0,l1);
  ((__nv_bfloat162*)Lp)[1] = __nv_bfloat162(l2,l3);
}

#define MMA16816(C, A, B) \
  asm volatile("mma.sync.aligned.m16n8k16.row.col.f32.bf16.bf16.f32 " \
    "{%0,%1,%2,%3}, {%4,%5,%6,%7}, {%8,%9}, {%0,%1,%2,%3};" \
    : "+f"((C)[0]),"+f"((C)[1]),"+f"((C)[2]),"+f"((C)[3]) \
    : "r"((A)[0]),"r"((A)[1]),"r"((A)[2]),"r"((A)[3]), "r"((B)[0]),"r"((B)[1]))

#define LDSM4(R, addr) \
  asm volatile("ldmatrix.sync.aligned.m8n8.x4.shared.b16 {%0,%1,%2,%3}, [%4];" \
    : "=r"((R)[0]),"=r"((R)[1]),"=r"((R)[2]),"=r"((R)[3]) : "r"(addr))

#define LDSM2(R, addr) \
  asm volatile("ldmatrix.sync.aligned.m8n8.x2.shared.b16 {%0,%1}, [%2];" \
    : "=r"((R)[0]),"=r"((R)[1]) : "r"(addr))

// transC=0: C[row][col]; transC=1: C[(row>>6)*N + col][row&63]
__launch_bounds__(256)
__global__ void tgemm_bias(const float* __restrict__ A, const float* __restrict__ W,
                           const float* __restrict__ b1, const float* __restrict__ b2,
                           float* __restrict__ C, int N, int K, int transC)
{
  __shared__ __nv_bfloat16 sm[2][4][128*GSTRIDE];
  const int tid = threadIdx.x;
  const int lane = tid & 31, warp = tid >> 5;
  const int warpM = (warp>>2)*64, warpN = (warp&3)*32;
  const int ctaM = blockIdx.y*128, ctaN = blockIdx.x*128;

  float acc[4][4][4];
#pragma unroll
  for (int mf=0;mf<4;mf++)
#pragma unroll
    for (int nf=0;nf<4;nf++)
#pragma unroll
      for (int i=0;i<4;i++) acc[mf][nf][i]=0.f;

  const float* Abase = A + (size_t)ctaM*K;
  const float* Wbase = W + (size_t)ctaN*K;
  const int r0 = tid>>2, kq = tid&3;
  const int sts_off = r0*GSTRIDE + kq*4;
  const int a_row = lane & 15, a_kh = (lane>>4)*8;
  const int b_row = lane & 7,  b_kh = ((lane>>3)&1)*8;

  unsigned smem_u32[2][4];
#pragma unroll
  for (int bf=0;bf<2;bf++)
#pragma unroll
    for (int q=0;q<4;q++) smem_u32[bf][q] = (unsigned)__cvta_generic_to_shared(sm[bf][q]);

  float4 ra0, ra1, rw0, rw1;
  ra0 = *(const float4*)(Abase + (size_t)r0*K + kq*4);
  ra1 = *(const float4*)(Abase + (size_t)(r0+64)*K + kq*4);
  rw0 = *(const float4*)(Wbase + (size_t)r0*K + kq*4);
  rw1 = *(const float4*)(Wbase + (size_t)(r0+64)*K + kq*4);
  cvt_store(&sm[0][0][sts_off],              &sm[0][1][sts_off],              ra0);
  cvt_store(&sm[0][0][sts_off+64*GSTRIDE],   &sm[0][1][sts_off+64*GSTRIDE],   ra1);
  cvt_store(&sm[0][2][sts_off],              &sm[0][3][sts_off],              rw0);
  cvt_store(&sm[0][2][sts_off+64*GSTRIDE],   &sm[0][3][sts_off+64*GSTRIDE],   rw1);
  __syncthreads();

  const int nchunk = K/16;
  for (int kc = 0; kc < nchunk; kc++){
    const int buf = kc & 1;
    if (kc+1 < nchunk){
      const float* ap = Abase + (kc+1)*16;
      const float* wp = Wbase + (kc+1)*16;
      ra0 = *(const float4*)(ap + (size_t)r0*K + kq*4);
      ra1 = *(const float4*)(ap + (size_t)(r0+64)*K + kq*4);
      rw0 = *(const float4*)(wp + (size_t)r0*K + kq*4);
      rw1 = *(const float4*)(wp + (size_t)(r0+64)*K + kq*4);
    }
    unsigned bh[4][2], bl[4][2];
#pragma unroll
    for (int nf=0;nf<4;nf++){
      unsigned off = (unsigned)((warpN + nf*8 + b_row)*GSTRIDE + b_kh)*2u;
      LDSM2(bh[nf], smem_u32[buf][2] + off);
      LDSM2(bl[nf], smem_u32[buf][3] + off);
    }
#pragma unroll
    for (int mf=0;mf<4;mf++){
      unsigned aoff = (unsigned)((warpM + mf*16 + a_row)*GSTRIDE + a_kh)*2u;
      unsigned ah[4], al[4];
      LDSM4(ah, smem_u32[buf][0] + aoff);
      LDSM4(al, smem_u32[buf][1] + aoff);
#pragma unroll
      for (int nf=0;nf<4;nf++){
        MMA16816(acc[mf][nf], ah, bh[nf]);
        MMA16816(acc[mf][nf], ah, bl[nf]);
        MMA16816(acc[mf][nf], al, bh[nf]);
      }
    }
    if (kc+1 < nchunk){
      const int nb = buf^1;
      cvt_store(&sm[nb][0][sts_off],            &sm[nb][1][sts_off],            ra0);
      cvt_store(&sm[nb][0][sts_off+64*GSTRIDE], &sm[nb][1][sts_off+64*GSTRIDE], ra1);
      cvt_store(&sm[nb][2][sts_off],            &sm[nb][3][sts_off],            rw0);
      cvt_store(&sm[nb][2][sts_off+64*GSTRIDE], &sm[nb][3][sts_off+64*GSTRIDE], rw1);
    }
    __syncthreads();
  }

#pragma unroll
  for (int nf=0;nf<4;nf++){
    int col = ctaN + warpN + nf*8 + (lane&3)*2;
    float bb0 = b1[col]   + (b2 ? b2[col]   : 0.f);
    float bb1 = b1[col+1] + (b2 ? b2[col+1] : 0.f);
#pragma unroll
    for (int mf=0;mf<4;mf++){
      int row = ctaM + warpM + mf*16 + (lane>>2);
      if (!transC){
        *(float2*)(C + (size_t)row*N + col)     = make_float2(acc[mf][nf][0]+bb0, acc[mf][nf][1]+bb1);
        *(float2*)(C + (size_t)(row+8)*N + col) = make_float2(acc[mf][nf][2]+bb0, acc[mf][nf][3]+bb1);
      } else {
        int s0 = row>>6, b0 = row&63;
        int s1 = (row+8)>>6, b1i = (row+8)&63;
        C[((size_t)s0*N + col  )*64 + b0 ] = acc[mf][nf][0]+bb0;
        C[((size_t)s0*N + col+1)*64 + b0 ] = acc[mf][nf][1]+bb1;
        C[((size_t)s1*N + col  )*64 + b1i] = acc[mf][nf][2]+bb0;
        C[((size_t)s1*N + col+1)*64 + b1i] = acc[mf][nf][3]+bb1;
      }
    }
  }
}

// ---------- LSTM v9 (champion): 128 CTAs x 256 thr ---------------------------
#define HST 520
#define WHI 0
#define WLO (16*HST)
#define HHI (32*HST)
#define HLO (96*HST)
#define REDOFF 41600
#define LS9_SMEM (160*HST*2 + 2*16*68*4)

extern __shared__ float ls_smem[];

__launch_bounds__(256, 1)
__global__ void lstm9_kernel(const float* __restrict__ W_hh)
{
  __nv_bfloat16* sb = (__nv_bfloat16*)ls_smem;
  float* red = ls_smem + REDOFF;

  const int t = threadIdx.x, lane = t&31, w = t>>5;
  const int c0 = blockIdx.x*4;
  const int mw = w&3, kh = w>>2;
  const int fj = t>>6, fb = t&63;
  const int a_row = lane & 15, a_kh = (lane>>4)*8;
  const int b_row = lane & 7,  b_kh = ((lane>>3)&1)*8;

  for (int id=t; id<16*512; id+=256){
    int row16 = id>>9, k = id&511;
    int gg = row16>>2, jj = row16&3;
    float v = W_hh[(size_t)(gg*DIM + c0 + jj)*DIM + k];
    __nv_bfloat16 hv = __float2bfloat16(v);
    sb[WHI + row16*HST + k] = hv;
    sb[WLO + row16*HST + k] = __float2bfloat16(v - __bfloat162float(hv));
  }
  float cstate = 0.f;
  __syncthreads();

  const unsigned sb_u = (unsigned)__cvta_generic_to_shared(sb);

  unsigned wfh[16][2][2], wfl[16][2][2];
#pragma unroll
  for (int ks=0; ks<16; ks++){
    const int kbase = kh*256 + ks*16;
#pragma unroll
    for (int nf=0;nf<2;nf++){
      unsigned bo = (unsigned)((nf*8 + b_row)*HST + kbase + b_kh)*2u;
      LDSM2(wfh[ks][nf], sb_u + (unsigned)(WHI*2) + bo);
      LDSM2(wfl[ks][nf], sb_u + (unsigned)(WLO*2) + bo);
    }
  }

  for (int s=0; s<SEQ; s++){
    const float* xgp = g_xg + ((size_t)s*G4 + (c0+fj))*64 + fb;
    float x0 = xgp[0], x1 = xgp[512*64], x2 = xgp[2*512*64], x3 = xgp[3*512*64];

    {
      const __nv_bfloat16* srcH = g_hhh + (size_t)s*BATCH*DIM;
      const __nv_bfloat16* srcL = g_hhl + (size_t)s*BATCH*DIM;
#pragma unroll
      for (int i=0;i<16;i++){
        int idx = lane + i*32;
        int row = idx>>5, ch = idx&31;
        int soff = (mw*16+row)*HST + kh*256 + ch*8;
        int goff = (mw*16+row)*512 + kh*256 + ch*8;
        cp16(sb + HHI + soff, srcH + goff);
        cp16(sb + HLO + soff, srcL + goff);
      }
      CP_COMMIT();
      CP_WAIT0();
      __syncwarp();
    }

    float acc[2][4];
#pragma unroll
    for (int nf=0;nf<2;nf++)
#pragma unroll
      for (int i=0;i<4;i++) acc[nf][i]=0.f;

#pragma unroll
    for (int ks=0; ks<16; ks++){
      const int kbase = kh*256 + ks*16;
      unsigned ah[4], al[4];
      unsigned aoff = (unsigned)((HHI) + (mw*16 + a_row)*HST + kbase + a_kh)*2u;
      unsigned loff = (unsigned)((HLO) + (mw*16 + a_row)*HST + kbase + a_kh)*2u;
      LDSM4(ah, sb_u + aoff);
      LDSM4(al, sb_u + loff);
#pragma unroll
      for (int nf=0;nf<2;nf++){
        MMA16816(acc[nf], ah, wfh[ks][nf]);
        MMA16816(acc[nf], ah, wfl[ks][nf]);
        MMA16816(acc[nf], al, wfh[ks][nf]);
      }
    }

#pragma unroll
    for (int nf=0;nf<2;nf++){
      int n0 = nf*8 + (lane&3)*2;
      int b0 = mw*16 + (lane>>2);
      red[(kh*16 + n0  )*68 + b0  ] = acc[nf][0];
      red[(kh*16 + n0+1)*68 + b0  ] = acc[nf][1];
      red[(kh*16 + n0  )*68 + b0+8] = acc[nf][2];
      red[(kh*16 + n0+1)*68 + b0+8] = acc[nf][3];
    }
    __syncthreads();

    {
      float gi=x0, gf=x1, gg2=x2, go=x3;
#pragma unroll
      for (int k2=0;k2<2;k2++){
        gi  += red[(k2*16 +  0 + fj)*68 + fb];
        gf  += red[(k2*16 +  4 + fj)*68 + fb];
        gg2 += red[(k2*16 +  8 + fj)*68 + fb];
        go  += red[(k2*16 + 12 + fj)*68 + fb];
      }
      cstate = sigf(gf)*cstate + sigf(gi)*tanhf(gg2);
      float hv = sigf(go)*tanhf(cstate);
      __nv_bfloat16 hh = __float2bfloat16(hv);
      size_t ho = (size_t)(s+1)*BATCH*DIM + fb*512 + c0 + fj;
      g_hhh[ho] = hh;
      g_hhl[ho] = __float2bfloat16(hv - __bfloat162float(hh));
    }
    __syncthreads();

    if (t==0){
      asm volatile("red.release.gpu.global.add.u32 [%0], %1;" ::
                   "l"(&g_bar), "r"(1u) : "memory");
      unsigned v;
      do {
        asm volatile("ld.acquire.gpu.global.u32 %0, [%1];" : "=r"(v) : "l"(&g_bar));
      } while (v < (unsigned)(s+1)*128u);
    }
    __syncthreads();
  }
}

// ---------- fused actions+tape: 512 CTAs x 64 thr ----------------------------
// CTA (bb,tp). Thread c holds W_act[tp*9..+8][c*8..c*8+7] in regs (loaded once),
// computes 9 act partials/step from the bf16 hi+lo h history (pipelined 1 step
// ahead), shfl-reduces, thread 0 does softmax/sigmoid, SMEM broadcast, then the
// register-resident tape update.
__launch_bounds__(64)
__global__ void tapeact_kernel(const float* __restrict__ W_act,
                               const float* __restrict__ b_act,
                               float* __restrict__ out)
{
  __shared__ float wpos[TL], rpos[TL], rpr[TL];
  __shared__ float pred[2][9];
  __shared__ float coef[9];
  __shared__ float bias9[9];
  const int bb = blockIdx.x>>3, tp = blockIdx.x&7, c = threadIdx.x;
  const int lane = c&31, wrp = c>>5;

  float wreg[9][8];
#pragma unroll
  for (int a=0;a<9;a++)
#pragma unroll
    for (int i=0;i<8;i++)
      wreg[a][i] = W_act[(size_t)(tp*9+a)*DIM + c*8+i];
  if (c<9) bias9[c] = b_act[tp*9+c];

  float tape[TL];
#pragma unroll
  for (int l=0;l<TL;l++) tape[l]=0.f;
  wpos[c] = (c==0)?1.f:0.f;
  rpos[c] = (c==0)?1.f:0.f;
  __syncthreads();

  // prefetch h(s=0) (history slot 1) and val(s=0)
  uint4 ph, pl; float cv;
  ph = *(const uint4*)(g_hhh + (size_t)1*BATCH*DIM + bb*512 + c*8);
  pl = *(const uint4*)(g_hhl + (size_t)1*BATCH*DIM + bb*512 + c*8);
  cv = g_val[(size_t)bb*DIM + tp*HD + c];

  for (int s=0;s<SEQ;s++){
    uint4 ch = ph, clv = pl; float v = cv;
    if (s+1 < SEQ){
      ph = *(const uint4*)(g_hhh + (size_t)(s+2)*BATCH*DIM + bb*512 + c*8);
      pl = *(const uint4*)(g_hhl + (size_t)(s+2)*BATCH*DIM + bb*512 + c*8);
      cv = g_val[((size_t)(s+1)*BATCH + bb)*DIM + tp*HD + c];
    }

    // h values (hi+lo) for this thread's k-slice
    float hv[8];
    {
      const __nv_bfloat162* h2 = (const __nv_bfloat162*)&ch;
      const __nv_bfloat162* l2 = (const __nv_bfloat162*)&clv;
#pragma unroll
      for (int i=0;i<4;i++){
        float2 a2 = __bfloat1622float2(h2[i]);
        float2 b2 = __bfloat1622float2(l2[i]);
        hv[2*i]   = a2.x + b2.x;
        hv[2*i+1] = a2.y + b2.y;
      }
    }
    float part[9];
#pragma unroll
    for (int a=0;a<9;a++){
      float s9 = 0.f;
#pragma unroll
      for (int i=0;i<8;i++) s9 += hv[i]*wreg[a][i];
      part[a] = s9;
    }
#pragma unroll
    for (int a=0;a<9;a++)
#pragma unroll
      for (int off=16; off>0; off>>=1)
        part[a] += __shfl_xor_sync(0xffffffffu, part[a], off);
    if (lane==0){
#pragma unroll
      for (int a=0;a<9;a++) pred[wrp][a] = part[a];
    }
    __syncthreads();
    if (c==0){
      float av[9];
#pragma unroll
      for (int a=0;a<9;a++) av[a] = pred[0][a]+pred[1][a]+bias9[a];
      float mr = fmaxf(av[0],fmaxf(av[1],av[2]));
      float e0=__expf(av[0]-mr), e1=__expf(av[1]-mr), e2=__expf(av[2]-mr);
      float ir = 1.f/(e0+e1+e2);
      coef[0]=e0*ir; coef[1]=e1*ir; coef[2]=e2*ir;
      float mw = fmaxf(av[3],fmaxf(av[4],av[5]));
      float f0=__expf(av[3]-mw), f1=__expf(av[4]-mw), f2=__expf(av[5]-mw);
      float iw = 1.f/(f0+f1+f2);
      coef[3]=f0*iw; coef[4]=f1*iw; coef[5]=f2*iw;
      coef[6]=sigf(av[6]); coef[7]=sigf(av[7]); coef[8]=sigf(av[8]);
    }
    __syncthreads();
    float rd0=coef[0], rd1=coef[1], rd2=coef[2];
    float wd0=coef[3], wd1=coef[4], wd2=coef[5];
    float rw0=coef[6], rw1=coef[7], rw2=coef[8];

    float oldv = 0.f;
#pragma unroll
    for (int l=0;l<TL;l++) oldv += tape[l]*wpos[l];

    float nw = wpos[(c+1)&63]*wd0 + wpos[c]*wd1 + wpos[(c+63)&63]*wd2;
    float nr = rpos[(c+1)&63]*rd0 + rpos[c]*rd1 + rpos[(c+63)&63]*rd2;
    rpr[c] = rpos[c]*rw0;
    __syncthreads();

    float upd = v*rw1 - oldv*rw2;
    float ro = 0.f;
#pragma unroll
    for (int l=0;l<TL;l++){
      tape[l] += wpos[l]*upd;
      ro += tape[l]*rpr[l];
    }
    __syncthreads();
    wpos[c]=nw; rpos[c]=nr;
    g_ro[((size_t)s*BATCH + bb)*DIM + tp*HD + c] = ro;
    __syncthreads();
  }
#pragma unroll
  for (int l=0;l<TL;l++)
    out[(size_t)SEQ*BATCH*DIM + ((size_t)l*BATCH + bb)*DIM + tp*HD + c] = tape[l];
}

extern "C" void kernel_launch(void* const* d_in, const int* in_sizes, int n_in,
                              void* d_out, int out_size)
{
  const float* inputs = (const float*)d_in[0];
  const float* W_ih   = (const float*)d_in[1];
  const float* W_hh   = (const float*)d_in[2];
  const float* b_ih   = (const float*)d_in[3];
  const float* b_hh   = (const float*)d_in[4];
  const float* W_act  = (const float*)d_in[5];
  const float* b_act  = (const float*)d_in[6];
  const float* W_val  = (const float*)d_in[7];
  const float* b_val  = (const float*)d_in[8];
  const float* W_out  = (const float*)d_in[9];
  const float* b_out  = (const float*)d_in[10];
  float* out = (float*)d_out;

  float *xg_p, *val_p, *ro_p;
  cudaGetSymbolAddress((void**)&xg_p,  g_xg);
  cudaGetSymbolAddress((void**)&val_p, g_val);
  cudaGetSymbolAddress((void**)&ro_p,  g_ro);

  cudaFuncSetAttribute(lstm9_kernel, cudaFuncAttributeMaxDynamicSharedMemorySize, LS9_SMEM);

  init_kernel<<<128,256>>>();
  tgemm_bias<<<dim3(16,256),256>>>(inputs, W_ih, b_ih, b_hh, xg_p, G4, DIM, 1);
  tgemm_bias<<<dim3(4,256),256>>>(inputs, W_val, b_val, nullptr, val_p, DIM, DIM, 0);
  lstm9_kernel<<<128,256,LS9_SMEM>>>(W_hh);
  tapeact_kernel<<<512,64>>>(W_act, b_act, out);
  tgemm_bias<<<dim3(4,256),256>>>(ro_p, W_out, b_out, nullptr, out, DIM, DIM, 0);
}